// round 15
// baseline (speedup 1.0000x reference)
#include <cuda_runtime.h>
#include <cstdint>

#define N_NODES 100000
#define D 128
#define CAP 32     // max per-(type,dest) degree stored (Poisson(<=4); P(>32) ~ 0)

// ---------------- device scratch (no allocations allowed) ----------------
__device__ int   g_L[(size_t)6 * N_NODES * CAP];  // bucket lists per (type,pos) block, ~77MB
__device__ int   g_cur[3 * N_NODES];              // cursor == per-type degree after scatter
__device__ float g_WT[7 * 128 * 128];             // transposed weight blocks (b=6 -> C_w)
__device__ unsigned int g_hi_or;                  // 0 => edge dtype is int64

// ---------------- helpers ----------------
__device__ __forceinline__ uint32_t f2tf(float f) {   // round-to-nearest tf32
    uint32_t r;
    asm("cvt.rna.tf32.f32 %0, %1;" : "=r"(r) : "f"(f));
    return r;
}

__device__ __forceinline__ int edge_at(const void* ei, long long pos, bool is64) {
    if (is64) return (int)((const long long*)ei)[pos];
    return ((const int*)ei)[pos];
}

// ---------------- zero cursors + dtype probe ----------------
__global__ void zero_kernel() {
    int i = blockIdx.x * blockDim.x + threadIdx.x;
    if (i < 3 * N_NODES) g_cur[i] = 0;
    if (i == 0) g_hi_or = 0u;
}

__global__ void detect_kernel(const void* __restrict__ e1) {
    const unsigned int* w = (const unsigned int*)e1;
    unsigned int v = w[2 * threadIdx.x + 1];
    for (int o = 16; o > 0; o >>= 1) v |= __shfl_down_sync(0xffffffffu, v, o);
    if ((threadIdx.x & 31) == 0 && v) atomicOr(&g_hi_or, v);
}

// ---------------- weight transpose: g_WT[b][n][k] = W_b[k][n] ----------------
struct WPtrs { const float* W[7]; };

__global__ void wt_kernel(WPtrs wp) {
    __shared__ float tile[32][33];
    int b  = blockIdx.y;
    int tr = (blockIdx.x >> 2) * 32;   // k base
    int tc = (blockIdx.x & 3)  * 32;   // n base
    const float* W = wp.W[b];
    int x = threadIdx.x, y = threadIdx.y;   // 32 x 8
#pragma unroll
    for (int i = 0; i < 32; i += 8)
        tile[y + i][x] = W[(size_t)(tr + y + i) * 128 + tc + x];
    __syncthreads();
    float* WT = g_WT + b * 16384;
#pragma unroll
    for (int i = 0; i < 32; i += 8)
        WT[(size_t)(tc + y + i) * 128 + tr + x] = tile[x][y + i];
}

// ---------------- bucket scatter: one thread per hyperedge ----------------
template <int S>
__global__ __launch_bounds__(256) void scatter_kernel(
    const void* __restrict__ ei, int n_edges, int lbase, int toff)
{
    int e = blockIdx.x * blockDim.x + threadIdx.x;
    if (e >= n_edges) return;
    bool is64 = (g_hi_or == 0u);

    long long n    = (long long)n_edges * S;
    long long base = (long long)e * S;
    int dest = edge_at(ei, n + base, is64);         // ei[1][e*S]
    int idx  = atomicAdd(&g_cur[toff + dest], 1);
    if (idx < CAP) {
#pragma unroll
        for (int p = 0; p < S; p++) {
            int src = edge_at(ei, base + p, is64);  // ei[0][e*S+p]
            g_L[((size_t)(lbase + p) * N_NODES + dest) * CAP + idx] = src;
        }
    }
}

// ---------------- fused aggregate + tf32 mma.sync GEMM ----------------
// Per CTA: 128 dest rows. For each weight block b: aggregate sum(x[src])/deg
// (or x itself for b==6) straight into SMEM As (tf32), then 4 K-chunks of MMA
// against W^T block b, accumulating in registers. One epilogue (+C_b).
#define ASTRIDE 132
#define BSTRIDE 36
#define SM_AS   0
#define SM_BS   (128 * ASTRIDE * 4)                 // 67584
#define SM_TOT  (SM_BS + 128 * BSTRIDE * 4)         // 86016 -> 2 CTAs/SM

__global__ __launch_bounds__(256, 2) void fused_kernel(
    const float* __restrict__ X, const float* __restrict__ Cb,
    float* __restrict__ out)
{
    extern __shared__ char smem[];
    uint32_t* As = (uint32_t*)(smem + SM_AS);
    uint32_t* Bs = (uint32_t*)(smem + SM_BS);

    const int t    = threadIdx.x;
    const int lane = t & 31;
    const int wid  = t >> 5;
    const int gid  = lane >> 2;     // 0..7
    const int tig  = lane & 3;      // 0..3
    const int m0   = blockIdx.x * 128;

    const int mbase = (wid & 3) * 32;    // warp m offset (epilogue/frag)
    const int nbase = (wid >> 2) * 64;   // warp n offset

    float acc[2][8][4];
#pragma unroll
    for (int mt = 0; mt < 2; mt++)
#pragma unroll
        for (int nt = 0; nt < 8; nt++)
#pragma unroll
            for (int r = 0; r < 4; r++) acc[mt][nt][r] = 0.f;

    for (int b = 0; b < 7; b++) {
        // ---- aggregate block b into As (each warp owns 16 dest rows) ----
#pragma unroll 1
        for (int rr = 0; rr < 16; rr++) {
            int r = wid * 16 + rr;
            int dest = m0 + r;
            float4 a = make_float4(0.f, 0.f, 0.f, 0.f);
            if (dest < N_NODES) {
                if (b == 6) {
                    a = ((const float4*)(X + (size_t)dest * D))[lane];
                } else {
                    int toff = (b == 0) ? 0 : (b < 3) ? N_NODES : 2 * N_NODES;
                    int deg = g_cur[toff + dest];
                    const int* lst = g_L + ((size_t)b * N_NODES + dest) * CAP;
                    int dn = min(deg, CAP);
#pragma unroll 4
                    for (int i = 0; i < dn; i++) {
                        int src = lst[i];
                        float4 v = ((const float4*)(X + (size_t)src * D))[lane];
                        a.x += v.x; a.y += v.y; a.z += v.z; a.w += v.w;
                    }
                    if (deg > 0) {
                        float inv = 1.0f / (float)deg;
                        a.x *= inv; a.y *= inv; a.z *= inv; a.w *= inv;
                    }
                }
            }
            uint32_t* da = As + r * ASTRIDE + lane * 4;
            asm volatile("st.shared.v4.b32 [%0], {%1, %2, %3, %4};"
                         :: "l"(__cvta_generic_to_shared(da)),
                            "r"(f2tf(a.x)), "r"(f2tf(a.y)),
                            "r"(f2tf(a.z)), "r"(f2tf(a.w)));
        }
        __syncthreads();

        // ---- 4 K-chunks of 32 against W^T block b ----
#pragma unroll 1
        for (int ck = 0; ck < 4; ck++) {
            const int koff = ck * 32;
            // stage Bs: 128 n-rows x 32 k (each thread 4 float4)
#pragma unroll
            for (int it = 0; it < 4; it++) {
                int slot = t + it * 256;
                int row = slot >> 3, f4 = slot & 7;
                float4 w = *(const float4*)(g_WT + b * 16384
                                            + (size_t)row * 128 + koff + f4 * 4);
                uint32_t* db = Bs + row * BSTRIDE + f4 * 4;
                db[0] = f2tf(w.x); db[1] = f2tf(w.y);
                db[2] = f2tf(w.z); db[3] = f2tf(w.w);
            }
            __syncthreads();

#pragma unroll
            for (int ks = 0; ks < 4; ks++) {
                const int ka = koff + ks * 8 + tig;   // absolute k in As
                const int kb = ks * 8 + tig;          // chunk-local k in Bs
                uint32_t a[2][4];
#pragma unroll
                for (int mt = 0; mt < 2; mt++) {
                    int rm = mbase + mt * 16;
                    a[mt][0] = As[(rm + gid)     * ASTRIDE + ka];
                    a[mt][1] = As[(rm + 8 + gid) * ASTRIDE + ka];
                    a[mt][2] = As[(rm + gid)     * ASTRIDE + ka + 4];
                    a[mt][3] = As[(rm + 8 + gid) * ASTRIDE + ka + 4];
                }
#pragma unroll
                for (int nt = 0; nt < 8; nt++) {
                    uint32_t b0 = Bs[(nbase + nt * 8 + gid) * BSTRIDE + kb];
                    uint32_t b1 = Bs[(nbase + nt * 8 + gid) * BSTRIDE + kb + 4];
#pragma unroll
                    for (int mt = 0; mt < 2; mt++) {
                        float* dd = acc[mt][nt];
                        asm volatile(
                            "mma.sync.aligned.m16n8k8.row.col.f32.tf32.tf32.f32 "
                            "{%0,%1,%2,%3}, {%4,%5,%6,%7}, {%8,%9}, {%0,%1,%2,%3};"
                            : "+f"(dd[0]), "+f"(dd[1]), "+f"(dd[2]), "+f"(dd[3])
                            : "r"(a[mt][0]), "r"(a[mt][1]), "r"(a[mt][2]), "r"(a[mt][3]),
                              "r"(b0), "r"(b1));
                    }
                }
            }
            __syncthreads();
        }
    }

    // ---- epilogue: out = acc + C_b ----
#pragma unroll
    for (int nt = 0; nt < 8; nt++) {
        int col = nbase + nt * 8 + 2 * tig;
        float cb0 = __ldg(&Cb[col]), cb1 = __ldg(&Cb[col + 1]);
#pragma unroll
        for (int mt = 0; mt < 2; mt++) {
            int m = m0 + mbase + mt * 16 + gid;
            if (m < N_NODES) {
                float2 v = make_float2(acc[mt][nt][0] + cb0, acc[mt][nt][1] + cb1);
                *(float2*)(out + (size_t)m * D + col) = v;
            }
            if (m + 8 < N_NODES) {
                float2 v = make_float2(acc[mt][nt][2] + cb0, acc[mt][nt][3] + cb1);
                *(float2*)(out + (size_t)(m + 8) * D + col) = v;
            }
        }
    }
}

// ---------------- launch ----------------
extern "C" void kernel_launch(void* const* d_in, const int* in_sizes, int n_in,
                              void* d_out, int out_size)
{
    const float *x = nullptr, *A1 = nullptr, *A2 = nullptr, *A3 = nullptr,
                *Cw = nullptr, *Cb = nullptr;
    const void *e1 = nullptr, *e2 = nullptr, *e3 = nullptr;

    for (int i = 0; i < n_in; i++) {
        int s = in_sizes[i];
        if      (s == 12800000) x  = (const float*)d_in[i];
        else if (s == 800000)   e1 = d_in[i];
        else if (s == 1200000)  { if (!e2) e2 = d_in[i];
                                  else      e3 = d_in[i]; }
        else if (s == 32768)    A2 = (const float*)d_in[i];
        else if (s == 49152)    A3 = (const float*)d_in[i];
        else if (s == 16384)    { if (!A1) A1 = (const float*)d_in[i];
                                  else      Cw = (const float*)d_in[i]; }
        else if (s == 128)      Cb = (const float*)d_in[i];
    }
    float* out = (float*)d_out;

    // 1) zero cursors + dtype probe + weight transpose
    zero_kernel<<<(3 * N_NODES + 255) / 256, 256>>>();
    detect_kernel<<<1, 128>>>(e1);
    WPtrs wp;
    wp.W[0] = A1;
    wp.W[1] = A2;               wp.W[2] = A2 + 128 * 128;
    wp.W[3] = A3;               wp.W[4] = A3 + 128 * 128;  wp.W[5] = A3 + 2 * 128 * 128;
    wp.W[6] = Cw;
    wt_kernel<<<dim3(16, 7), dim3(32, 8)>>>(wp);

    // 2) bucket scatter (thread per hyperedge); cursor becomes per-type degree
    scatter_kernel<1><<<(400000 + 255) / 256, 256>>>(e1, 400000, 0, 0);
    scatter_kernel<2><<<(300000 + 255) / 256, 256>>>(e2, 300000, 1, N_NODES);
    scatter_kernel<3><<<(200000 + 255) / 256, 256>>>(e3, 200000, 3, 2 * N_NODES);

    // 3) fused aggregate + GEMM -> out
    cudaFuncSetAttribute(fused_kernel,
                         cudaFuncAttributeMaxDynamicSharedMemorySize, SM_TOT);
    fused_kernel<<<(N_NODES + 127) / 128, 256, SM_TOT>>>(x, Cb, out);
}

// round 17
// speedup vs baseline: 1.0366x; 1.0366x over previous
#include <cuda_runtime.h>
#include <cstdint>

#define N_NODES 100000
#define D 128
#define CAP 32     // max per-(type,dest) degree stored (Poisson(<=4); P(>32) ~ 0)

// ---------------- device scratch (no allocations allowed) ----------------
__device__ int   g_L[(size_t)6 * N_NODES * CAP];  // bucket lists per (type,pos) block, ~77MB
__device__ int   g_cur[3 * N_NODES];              // cursor == per-type degree after scatter
__device__ float g_WT[7 * 128 * 128];             // transposed weight blocks (b=6 -> C_w)
__device__ unsigned int g_hi_or;                  // 0 => edge dtype is int64

// ---------------- helpers ----------------
__device__ __forceinline__ uint32_t f2tf(float f) {   // round-to-nearest tf32
    uint32_t r;
    asm("cvt.rna.tf32.f32 %0, %1;" : "=r"(r) : "f"(f));
    return r;
}

__device__ __forceinline__ int edge_at(const void* ei, long long pos, bool is64) {
    if (is64) return (int)((const long long*)ei)[pos];
    return ((const int*)ei)[pos];
}

// ---------------- zero cursors + dtype probe ----------------
__global__ void zero_kernel() {
    int i = blockIdx.x * blockDim.x + threadIdx.x;
    if (i < 3 * N_NODES) g_cur[i] = 0;
    if (i == 0) g_hi_or = 0u;
}

__global__ void detect_kernel(const void* __restrict__ e1) {
    const unsigned int* w = (const unsigned int*)e1;
    unsigned int v = w[2 * threadIdx.x + 1];
    for (int o = 16; o > 0; o >>= 1) v |= __shfl_down_sync(0xffffffffu, v, o);
    if ((threadIdx.x & 31) == 0 && v) atomicOr(&g_hi_or, v);
}

// ---------------- weight transpose: g_WT[b][n][k] = W_b[k][n] ----------------
struct WPtrs { const float* W[7]; };

__global__ void wt_kernel(WPtrs wp) {
    __shared__ float tile[32][33];
    int b  = blockIdx.y;
    int tr = (blockIdx.x >> 2) * 32;   // k base
    int tc = (blockIdx.x & 3)  * 32;   // n base
    const float* W = wp.W[b];
    int x = threadIdx.x, y = threadIdx.y;   // 32 x 8
#pragma unroll
    for (int i = 0; i < 32; i += 8)
        tile[y + i][x] = W[(size_t)(tr + y + i) * 128 + tc + x];
    __syncthreads();
    float* WT = g_WT + b * 16384;
#pragma unroll
    for (int i = 0; i < 32; i += 8)
        WT[(size_t)(tc + y + i) * 128 + tr + x] = tile[x][y + i];
}

// ---------------- bucket scatter: one thread per hyperedge ----------------
template <int S>
__global__ __launch_bounds__(256) void scatter_kernel(
    const void* __restrict__ ei, int n_edges, int lbase, int toff)
{
    int e = blockIdx.x * blockDim.x + threadIdx.x;
    if (e >= n_edges) return;
    bool is64 = (g_hi_or == 0u);

    long long n    = (long long)n_edges * S;
    long long base = (long long)e * S;
    int dest = edge_at(ei, n + base, is64);         // ei[1][e*S]
    int idx  = atomicAdd(&g_cur[toff + dest], 1);
    if (idx < CAP) {
#pragma unroll
        for (int p = 0; p < S; p++) {
            int src = edge_at(ei, base + p, is64);  // ei[0][e*S+p]
            g_L[((size_t)(lbase + p) * N_NODES + dest) * CAP + idx] = src;
        }
    }
}

// ---------------- fused aggregate + tf32 mma.sync GEMM ----------------
// Per CTA: 128 dest rows. For each weight block b: aggregate sum(x[src])/deg
// (or x itself for b==6) straight into SMEM As (tf32), then 4 K-chunks of MMA
// against W^T block b, accumulating in registers. One epilogue (+C_b).
// Gather is MLP-batched: 1 coalesced list load/row + 8 independent X loads.
#define ASTRIDE 132
#define BSTRIDE 36
#define SM_AS   0
#define SM_BS   (128 * ASTRIDE * 4)                 // 67584
#define SM_TOT  (SM_BS + 128 * BSTRIDE * 4)         // 86016 -> 2 CTAs/SM

__global__ __launch_bounds__(256, 2) void fused_kernel(
    const float* __restrict__ X, const float* __restrict__ Cb,
    float* __restrict__ out)
{
    extern __shared__ char smem[];
    uint32_t* As = (uint32_t*)(smem + SM_AS);
    uint32_t* Bs = (uint32_t*)(smem + SM_BS);

    const int t    = threadIdx.x;
    const int lane = t & 31;
    const int wid  = t >> 5;
    const int gid  = lane >> 2;     // 0..7
    const int tig  = lane & 3;      // 0..3
    const int m0   = blockIdx.x * 128;

    const int mbase = (wid & 3) * 32;    // warp m offset (epilogue/frag)
    const int nbase = (wid >> 2) * 64;   // warp n offset

    float acc[2][8][4];
#pragma unroll
    for (int mt = 0; mt < 2; mt++)
#pragma unroll
        for (int nt = 0; nt < 8; nt++)
#pragma unroll
            for (int r = 0; r < 4; r++) acc[mt][nt][r] = 0.f;

    for (int b = 0; b < 7; b++) {
        // ---- aggregate block b into As (each warp owns 16 dest rows) ----
        const int toff = (b == 0) ? 0 : (b < 3) ? N_NODES : 2 * N_NODES;
#pragma unroll 1
        for (int rr = 0; rr < 16; rr++) {
            int r = wid * 16 + rr;
            int dest = m0 + r;
            float4 a = make_float4(0.f, 0.f, 0.f, 0.f);
            if (dest < N_NODES) {
                if (b == 6) {
                    a = ((const float4*)(X + (size_t)dest * D))[lane];
                } else {
                    int deg = g_cur[toff + dest];
                    int dn = min(deg, CAP);
                    if (dn > 0) {
                        // one coalesced list load (CAP==32 => lane i gets lst[i])
                        const int* lst = g_L + ((size_t)b * N_NODES + dest) * CAP;
                        int myl = lst[min(lane, dn - 1)];
#pragma unroll 1
                        for (int i0 = 0; i0 < dn; i0 += 8) {
                            // 8 independent gathers, validity folded in as FMA mask
                            float4 v[8];
                            float  msk[8];
#pragma unroll
                            for (int j = 0; j < 8; j++) {
                                int idx = i0 + j;
                                int src = __shfl_sync(0xffffffffu, myl,
                                                      min(idx, dn - 1));
                                msk[j] = (idx < dn) ? 1.f : 0.f;
                                v[j] = ((const float4*)(X + (size_t)src * D))[lane];
                            }
#pragma unroll
                            for (int j = 0; j < 8; j++) {
                                a.x = fmaf(v[j].x, msk[j], a.x);
                                a.y = fmaf(v[j].y, msk[j], a.y);
                                a.z = fmaf(v[j].z, msk[j], a.z);
                                a.w = fmaf(v[j].w, msk[j], a.w);
                            }
                        }
                        float inv = 1.0f / (float)deg;
                        a.x *= inv; a.y *= inv; a.z *= inv; a.w *= inv;
                    }
                }
            }
            uint32_t* da = As + r * ASTRIDE + lane * 4;
            asm volatile("st.shared.v4.b32 [%0], {%1, %2, %3, %4};"
                         :: "l"(__cvta_generic_to_shared(da)),
                            "r"(f2tf(a.x)), "r"(f2tf(a.y)),
                            "r"(f2tf(a.z)), "r"(f2tf(a.w)));
        }
        __syncthreads();

        // ---- 4 K-chunks of 32 against W^T block b ----
#pragma unroll 1
        for (int ck = 0; ck < 4; ck++) {
            const int koff = ck * 32;
            // stage Bs: 128 n-rows x 32 k (each thread 4 float4)
#pragma unroll
            for (int it = 0; it < 4; it++) {
                int slot = t + it * 256;
                int row = slot >> 3, f4 = slot & 7;
                float4 w = *(const float4*)(g_WT + b * 16384
                                            + (size_t)row * 128 + koff + f4 * 4);
                uint32_t* db = Bs + row * BSTRIDE + f4 * 4;
                db[0] = f2tf(w.x); db[1] = f2tf(w.y);
                db[2] = f2tf(w.z); db[3] = f2tf(w.w);
            }
            __syncthreads();

#pragma unroll
            for (int ks = 0; ks < 4; ks++) {
                const int ka = koff + ks * 8 + tig;   // absolute k in As
                const int kb = ks * 8 + tig;          // chunk-local k in Bs
                uint32_t a[2][4];
#pragma unroll
                for (int mt = 0; mt < 2; mt++) {
                    int rm = mbase + mt * 16;
                    a[mt][0] = As[(rm + gid)     * ASTRIDE + ka];
                    a[mt][1] = As[(rm + 8 + gid) * ASTRIDE + ka];
                    a[mt][2] = As[(rm + gid)     * ASTRIDE + ka + 4];
                    a[mt][3] = As[(rm + 8 + gid) * ASTRIDE + ka + 4];
                }
#pragma unroll
                for (int nt = 0; nt < 8; nt++) {
                    uint32_t b0 = Bs[(nbase + nt * 8 + gid) * BSTRIDE + kb];
                    uint32_t b1 = Bs[(nbase + nt * 8 + gid) * BSTRIDE + kb + 4];
#pragma unroll
                    for (int mt = 0; mt < 2; mt++) {
                        float* dd = acc[mt][nt];
                        asm volatile(
                            "mma.sync.aligned.m16n8k8.row.col.f32.tf32.tf32.f32 "
                            "{%0,%1,%2,%3}, {%4,%5,%6,%7}, {%8,%9}, {%0,%1,%2,%3};"
                            : "+f"(dd[0]), "+f"(dd[1]), "+f"(dd[2]), "+f"(dd[3])
                            : "r"(a[mt][0]), "r"(a[mt][1]), "r"(a[mt][2]), "r"(a[mt][3]),
                              "r"(b0), "r"(b1));
                    }
                }
            }
            __syncthreads();
        }
    }

    // ---- epilogue: out = acc + C_b ----
#pragma unroll
    for (int nt = 0; nt < 8; nt++) {
        int col = nbase + nt * 8 + 2 * tig;
        float cb0 = __ldg(&Cb[col]), cb1 = __ldg(&Cb[col + 1]);
#pragma unroll
        for (int mt = 0; mt < 2; mt++) {
            int m = m0 + mbase + mt * 16 + gid;
            if (m < N_NODES) {
                float2 v = make_float2(acc[mt][nt][0] + cb0, acc[mt][nt][1] + cb1);
                *(float2*)(out + (size_t)m * D + col) = v;
            }
            if (m + 8 < N_NODES) {
                float2 v = make_float2(acc[mt][nt][2] + cb0, acc[mt][nt][3] + cb1);
                *(float2*)(out + (size_t)(m + 8) * D + col) = v;
            }
        }
    }
}

// ---------------- launch ----------------
extern "C" void kernel_launch(void* const* d_in, const int* in_sizes, int n_in,
                              void* d_out, int out_size)
{
    const float *x = nullptr, *A1 = nullptr, *A2 = nullptr, *A3 = nullptr,
                *Cw = nullptr, *Cb = nullptr;
    const void *e1 = nullptr, *e2 = nullptr, *e3 = nullptr;

    for (int i = 0; i < n_in; i++) {
        int s = in_sizes[i];
        if      (s == 12800000) x  = (const float*)d_in[i];
        else if (s == 800000)   e1 = d_in[i];
        else if (s == 1200000)  { if (!e2) e2 = d_in[i];
                                  else      e3 = d_in[i]; }
        else if (s == 32768)    A2 = (const float*)d_in[i];
        else if (s == 49152)    A3 = (const float*)d_in[i];
        else if (s == 16384)    { if (!A1) A1 = (const float*)d_in[i];
                                  else      Cw = (const float*)d_in[i]; }
        else if (s == 128)      Cb = (const float*)d_in[i];
    }
    float* out = (float*)d_out;

    // 1) zero cursors + dtype probe + weight transpose
    zero_kernel<<<(3 * N_NODES + 255) / 256, 256>>>();
    detect_kernel<<<1, 128>>>(e1);
    WPtrs wp;
    wp.W[0] = A1;
    wp.W[1] = A2;               wp.W[2] = A2 + 128 * 128;
    wp.W[3] = A3;               wp.W[4] = A3 + 128 * 128;  wp.W[5] = A3 + 2 * 128 * 128;
    wp.W[6] = Cw;
    wt_kernel<<<dim3(16, 7), dim3(32, 8)>>>(wp);

    // 2) bucket scatter (thread per hyperedge); cursor becomes per-type degree
    scatter_kernel<1><<<(400000 + 255) / 256, 256>>>(e1, 400000, 0, 0);
    scatter_kernel<2><<<(300000 + 255) / 256, 256>>>(e2, 300000, 1, N_NODES);
    scatter_kernel<3><<<(200000 + 255) / 256, 256>>>(e3, 200000, 3, 2 * N_NODES);

    // 3) fused aggregate + GEMM -> out
    cudaFuncSetAttribute(fused_kernel,
                         cudaFuncAttributeMaxDynamicSharedMemorySize, SM_TOT);
    fused_kernel<<<(N_NODES + 127) / 128, 256, SM_TOT>>>(x, Cb, out);
}